// round 13
// baseline (speedup 1.0000x reference)
#include <cuda_runtime.h>
#include <cuda_bf16.h>
#include <cuda_fp16.h>
#include <math.h>

// Problem constants
#define BB 64
#define TT 512
#define ENC 512
#define HH 256
#define G4 1024
#define PD 128
#define XK 640          // POS_DIM + ENC
#define LAB 128
#define VK 768          // HH + ENC
#define BT (BB*TT)      // 32768
#define NOUT (BT*LAB)   // 4194304

typedef unsigned long long ull;

// ---------------- device scratch (allocation-free rule: __device__ globals) ----------
__device__ __align__(16) float g_cse[(size_t)BT*ENC];
__device__ __align__(16) float g_X[(size_t)BT*XK];
__device__ __align__(16) float g_z[(size_t)BT*HH];
__device__ __align__(16) float g_gin[(size_t)BT*G4];
__device__ __align__(16) float g_wT[256*1024];         // w_hh^T fp32 [k][j] for scan
__device__ __align__(16) float g_hch[(size_t)BT*HH];   // compact chain h
__device__ __align__(16) float g_cch[(size_t)BT*HH];   // compact chain c
__device__ __align__(16) float g_P[(size_t)BT*G4];     // h_chain @ w_hh^T per node
__device__ __align__(16) float g_hs[(size_t)BT*HH];
__device__ __align__(16) float g_logits[(size_t)BT*LAB];
__device__ int g_svec[BT];
__device__ int g_rank[BT];     // LOCAL (per-row) chain rank, -1 if none
__device__ int g_tb[BT];       // per-row sep positions
__device__ int g_nb[BB];
__device__ int g_off[BB];      // global compact offset per row
__device__ int g_total;        // total chain nodes

__device__ __forceinline__ float sigmf(float x) { return 1.0f / (1.0f + expf(-x)); }

// ---- packed f32x2 helpers ----------------------------------------------------------
__device__ __forceinline__ ull fma2(ull a, ull b, ull c) {
    ull d; asm("fma.rn.f32x2 %0, %1, %2, %3;" : "=l"(d) : "l"(a), "l"(b), "l"(c)); return d;
}
__device__ __forceinline__ ull pack2(float x, float y) {
    ull r; asm("mov.b64 %0, {%1, %2};" : "=l"(r) : "f"(x), "f"(y)); return r;
}
__device__ __forceinline__ float2 unpack2(ull v) {
    float2 r; asm("mov.b64 {%0, %1}, %2;" : "=f"(r.x), "=f"(r.y) : "l"(v)); return r;
}
__device__ __forceinline__ unsigned packbf(float lo, float hi) {
    __nv_bfloat162 t = __float22bfloat162_rn(make_float2(lo, hi));
    return *reinterpret_cast<unsigned*>(&t);
}
__device__ __forceinline__ void mma_bf16(float* c, const unsigned* a, unsigned b0, unsigned b1) {
    asm("mma.sync.aligned.m16n8k16.row.col.f32.bf16.bf16.f32 "
        "{%0,%1,%2,%3}, {%4,%5,%6,%7}, {%8,%9}, {%0,%1,%2,%3};"
        : "+f"(c[0]), "+f"(c[1]), "+f"(c[2]), "+f"(c[3])
        : "r"(a[0]), "r"(a[1]), "r"(a[2]), "r"(a[3]), "r"(b0), "r"(b1));
}

// ---------------- prep: warp-ballot scan per batch row ------------------------------
__global__ void k_prep(const int* __restrict__ bd) {
    int wid = threadIdx.x >> 5;
    int lane = threadIdx.x & 31;
    int b = blockIdx.x * 32 + wid;
    if (b >= BB) return;
    int prev_last = -1, prev_cnt = 0;
    for (int c = 0; c < 16; c++) {
        int t = c*32 + lane;
        int bval = bd[b*TT + t];
        int bit = (t < TT-1) && (bval == 1);   // sep at t=511 never referenced
        unsigned mask = __ballot_sync(0xffffffffu, bit);
        unsigned low = mask & ((1u << lane) - 1u);
        int cnt_before = prev_cnt + __popc(low);
        int s = low ? (c*32 + 31 - __clz(low)) : prev_last;
        g_svec[b*TT + t] = s < 0 ? 0 : s;
        g_rank[b*TT + t] = cnt_before - 1;
        if (bit) g_tb[b*TT + cnt_before] = t;
        prev_cnt += __popc(mask);
        if (mask) prev_last = c*32 + 31 - __clz(mask);
    }
    if (lane == 0) g_nb[b] = prev_cnt;
}

__global__ void k_off() {
    int o = 0;
    for (int i = 0; i < BB; i++) { g_off[i] = o; o += g_nb[i]; }
    g_total = o;
}

// ---------------- transpose w_hh -> fp32 [k][j] for scan -----------------------------
__global__ void k_transpose(const float* __restrict__ whh) {
    int idx = blockIdx.x * blockDim.x + threadIdx.x;  // 262144
    int k = idx >> 10, j = idx & 1023;
    g_wT[idx] = whh[j*HH + k];
}

// ---------------- exclusive prefix sum over time, per (b, feature) ------------------
__global__ void k_cse(const float* __restrict__ enc) {
    int b = blockIdx.x;
    int d = blockIdx.y * 128 + threadIdx.x;
    float acc = 0.0f;
    size_t base = (size_t)b * TT * ENC + d;
    #pragma unroll 8
    for (int t = 0; t < TT; t++) {
        size_t idx = base + (size_t)t * ENC;
        g_cse[idx] = acc;
        acc += enc[idx];
    }
}

// ---------------- build X = [pos_emb(128), pooled_mean(512)] ------------------------
__global__ void k_buildX(const int* __restrict__ pos_seq, const float* __restrict__ pos_table) {
    int m = blockIdx.x;             // (b,t)
    int tid = threadIdx.x;          // 640
    int b = m >> 9, t = m & 511;
    int s = g_svec[m];
    if (tid < PD) {
        int p = pos_seq[b*TT + s];
        g_X[(size_t)m*XK + tid] = pos_table[p*PD + tid];
    } else {
        int d = tid - PD;
        float wl = (float)((t - s) > 1 ? (t - s) : 1);
        float v = (g_cse[(size_t)m*ENC + d] - g_cse[((size_t)(b*TT + s))*ENC + d]) / wl;
        g_X[(size_t)m*XK + tid] = v;
    }
}

// ---------------- bf16 tensor-core GEMM, C = A @ W^T, 128x128 CTA tile ---------------
// MODE 0: z = tanh(X @ cw^T + cb), zeroed at t==0          (K=640)
// MODE 1: gin = z @ w_ih^T + b_ih + b_hh                    (K=256)
// MODE 2: P = hchain @ w_hh^T  (over g_total compact rows)  (K=256)
// MODE 3: logits = [hs, enc] @ lw^T                         (K=768)
#define KT 32
#define SU 20    // smem row stride in uint (bf16x2) units: 32 halves data + 8 pad
template<int MODE>
__global__ void __launch_bounds__(256, 2) gemm_k(const float* __restrict__ W,
                                                 const float* __restrict__ b1,
                                                 const float* __restrict__ b2,
                                                 const float* __restrict__ enc,
                                                 int K) {
    __shared__ __align__(16) unsigned As[2][128*SU];
    __shared__ __align__(16) unsigned Ws[2][128*SU];
    int tid = threadIdx.x;
    int m0 = blockIdx.x * 128, n0 = blockIdx.y * 128;
    if (MODE == 2) { if (m0 >= g_total) return; }
    const float* A = (MODE == 0) ? g_X : (MODE == 1) ? g_z : (MODE == 2) ? g_hch : g_hs;

    int lr = tid >> 1;            // load row 0..127
    int lc = (tid & 1) * 16;      // float col base 0/16

    auto loadA = [&](int k0, float4* v) {
        const float* base;
        if (MODE == 3) {
            int gk = k0 + lc;     // 16-aligned; never straddles the 256 boundary
            if (gk < HH) base = g_hs + (size_t)(m0 + lr)*HH + gk;
            else         base = enc  + (size_t)(m0 + lr)*ENC + (gk - HH);
        } else {
            base = A + (size_t)(m0 + lr)*K + k0 + lc;
        }
        v[0] = *reinterpret_cast<const float4*>(base);
        v[1] = *reinterpret_cast<const float4*>(base + 4);
        v[2] = *reinterpret_cast<const float4*>(base + 8);
        v[3] = *reinterpret_cast<const float4*>(base + 12);
    };
    auto loadW = [&](int k0, float4* v) {
        const float* base = W + (size_t)(n0 + lr)*K + k0 + lc;
        v[0] = *reinterpret_cast<const float4*>(base);
        v[1] = *reinterpret_cast<const float4*>(base + 4);
        v[2] = *reinterpret_cast<const float4*>(base + 8);
        v[3] = *reinterpret_cast<const float4*>(base + 12);
    };
    auto stTile = [&](unsigned* dst, const float4* v) {
        int o = lr*SU + (tid & 1)*8;
        #pragma unroll
        for (int i = 0; i < 4; i++) {
            dst[o + 2*i]     = packbf(v[i].x, v[i].y);
            dst[o + 2*i + 1] = packbf(v[i].z, v[i].w);
        }
    };

    int lane = tid & 31, wid = tid >> 5;
    int wm = wid >> 1, wn = wid & 1;       // warp tile: 32(M) x 64(N)
    int qr = lane >> 2, qc = lane & 3;

    float acc[2][8][4];
    #pragma unroll
    for (int i = 0; i < 2; i++)
        #pragma unroll
        for (int j = 0; j < 8; j++)
            #pragma unroll
            for (int e = 0; e < 4; e++) acc[i][j][e] = 0.0f;

    int abase = (wm*32 + qr)*SU + qc;
    int bbase = (wn*64 + qr)*SU + qc;

    float4 av[4], wv[4];
    loadA(0, av); loadW(0, wv);
    stTile(As[0], av); stTile(Ws[0], wv);
    __syncthreads();
    int p = 0;
    int nk = K / KT;

    for (int kt = 0; kt < nk; kt++) {
        bool has_next = (kt + 1 < nk);
        if (has_next) { loadA((kt+1)*KT, av); loadW((kt+1)*KT, wv); }
        const unsigned* ap = As[p];
        const unsigned* wp = Ws[p];
        #pragma unroll
        for (int g = 0; g < 2; g++) {          // two k16 groups per KT=32 tile
            unsigned af[2][4];
            #pragma unroll
            for (int i = 0; i < 2; i++) {
                int o = abase + i*16*SU + g*8;
                af[i][0] = ap[o];
                af[i][1] = ap[o + 8*SU];
                af[i][2] = ap[o + 4];
                af[i][3] = ap[o + 8*SU + 4];
            }
            #pragma unroll
            for (int j = 0; j < 8; j++) {
                int o = bbase + j*8*SU + g*8;
                unsigned bf0 = wp[o];
                unsigned bf1 = wp[o + 4];
                mma_bf16(acc[0][j], af[0], bf0, bf1);
                mma_bf16(acc[1][j], af[1], bf0, bf1);
            }
        }
        if (has_next) {
            int q = p ^ 1;
            stTile(As[q], av); stTile(Ws[q], wv);
            __syncthreads();
            p = q;
        }
    }

    // epilogue: c0:(r, 2qc) c1:(r, 2qc+1) c2:(r+8, 2qc) c3:(r+8, 2qc+1)
    #pragma unroll
    for (int i = 0; i < 2; i++) {
        #pragma unroll
        for (int j = 0; j < 8; j++) {
            int mb = m0 + wm*32 + i*16 + qr;
            int nb = n0 + wn*64 + j*8 + qc*2;
            #pragma unroll
            for (int e = 0; e < 4; e++) {
                int m = mb + (e >> 1)*8;
                int n = nb + (e & 1);
                float v = acc[i][j][e];
                if (MODE == 0) {
                    v = tanhf(v + b1[n]);
                    if ((m & 511) == 0) v = 0.0f;
                    g_z[(size_t)m*HH + n] = v;
                } else if (MODE == 1) {
                    g_gin[(size_t)m*G4 + n] = v + b1[n] + b2[n];
                } else if (MODE == 2) {
                    g_P[(size_t)m*G4 + n] = v;
                } else {
                    g_logits[(size_t)m*LAB + n] = v;
                }
            }
        }
    }
}

// ------- sequential LSTM over compacted boundary chains, 2 rows/CTA, f32x2 FMA -------
__global__ void __launch_bounds__(256) k_scan2() {
    int b0 = blockIdx.x * 2;
    int b1 = b0 + 1;
    int tid = threadIdx.x;          // 256
    int q = tid >> 6;               // gate quadrant (i,f,g,o)
    int u4 = (tid & 63) << 2;       // 4-unit group
    int gi0 = q*HH + u4;
    __shared__ __align__(16) ull sh_h2[2][HH];   // (h,h) duplicated pairs
    __shared__ float sh_g[2][G4];
    sh_h2[0][tid] = 0ull;
    sh_h2[1][tid] = 0ull;
    float c0 = 0.0f, c1 = 0.0f;
    __syncthreads();
    int n0 = g_nb[b0], n1 = g_nb[b1];
    int off0 = g_off[b0], off1 = g_off[b1];
    int nmax = n0 > n1 ? n0 : n1;
    const float* wb = g_wT + gi0;
    for (int k = 0; k < nmax; k++) {
        bool a0 = (k < n0), a1 = (k < n1);
        ull acc00 = 0, acc01 = 0, acc10 = 0, acc11 = 0;
        if (a0) {
            int t = g_tb[b0*TT + k];
            float4 gv = *reinterpret_cast<const float4*>(g_gin + ((size_t)(b0*TT + t))*G4 + gi0);
            acc00 = pack2(gv.x, gv.y); acc01 = pack2(gv.z, gv.w);
        }
        if (a1) {
            int t = g_tb[b1*TT + k];
            float4 gv = *reinterpret_cast<const float4*>(g_gin + ((size_t)(b1*TT + t))*G4 + gi0);
            acc10 = pack2(gv.x, gv.y); acc11 = pack2(gv.z, gv.w);
        }
        #pragma unroll 8
        for (int kk = 0; kk < HH; kk++) {
            ulonglong2 w = *reinterpret_cast<const ulonglong2*>(wb + kk*G4);
            ull h0 = sh_h2[0][kk];
            ull h1 = sh_h2[1][kk];
            acc00 = fma2(h0, w.x, acc00); acc01 = fma2(h0, w.y, acc01);
            acc10 = fma2(h1, w.x, acc10); acc11 = fma2(h1, w.y, acc11);
        }
        float2 p00 = unpack2(acc00), p01 = unpack2(acc01);
        float2 p10 = unpack2(acc10), p11 = unpack2(acc11);
        sh_g[0][gi0+0] = p00.x; sh_g[0][gi0+1] = p00.y; sh_g[0][gi0+2] = p01.x; sh_g[0][gi0+3] = p01.y;
        sh_g[1][gi0+0] = p10.x; sh_g[1][gi0+1] = p10.y; sh_g[1][gi0+2] = p11.x; sh_g[1][gi0+3] = p11.y;
        __syncthreads();
        if (a0) {
            float xi = sh_g[0][tid], xf = sh_g[0][HH + tid];
            float xg = sh_g[0][2*HH + tid], xo = sh_g[0][3*HH + tid];
            float cc = sigmf(xf)*c0 + sigmf(xi)*tanhf(xg);
            float hh = sigmf(xo)*tanhf(cc);
            c0 = cc;
            sh_h2[0][tid] = pack2(hh, hh);
            size_t o = ((size_t)(off0 + k))*HH + tid;
            g_hch[o] = hh; g_cch[o] = cc;
        }
        if (a1) {
            float xi = sh_g[1][tid], xf = sh_g[1][HH + tid];
            float xg = sh_g[1][2*HH + tid], xo = sh_g[1][3*HH + tid];
            float cc = sigmf(xf)*c1 + sigmf(xi)*tanhf(xg);
            float hh = sigmf(xo)*tanhf(cc);
            c1 = cc;
            sh_h2[1][tid] = pack2(hh, hh);
            size_t o = ((size_t)(off1 + k))*HH + tid;
            g_hch[o] = hh; g_cch[o] = cc;
        }
        __syncthreads();
    }
}

// ---------------- pointwise LSTM cell over all (b,t), fused carry gather -------------
__global__ void k_lstm() {
    int idx = blockIdx.x * blockDim.x + threadIdx.x;  // BT*256
    int m = idx >> 8, u = idx & 255;
    int b = m >> 9;
    int r = g_rank[m];
    size_t gb = (size_t)m*G4 + u;
    float xi = g_gin[gb], xf = g_gin[gb + HH], xg = g_gin[gb + 2*HH], xo = g_gin[gb + 3*HH];
    float c_sep = 0.0f;
    if (r >= 0) {
        size_t node = (size_t)(g_off[b] + r);
        size_t pb = node*G4 + u;
        xi += g_P[pb]; xf += g_P[pb + HH]; xg += g_P[pb + 2*HH]; xo += g_P[pb + 3*HH];
        c_sep = g_cch[node*HH + u];
    }
    float cc = sigmf(xf)*c_sep + sigmf(xi)*tanhf(xg);
    g_hs[idx] = sigmf(xo)*tanhf(cc);
}

// ---------------- masks + log_softmax + output write --------------------------------
__global__ void k_softmax(const int* __restrict__ lengths, float* __restrict__ out, int dual) {
    int m = blockIdx.x;
    int l = threadIdx.x;   // 128
    int t = m & 511, b = m >> 9;
    float x = g_logits[(size_t)m*LAB + l];
    if (t == 0 && l == 0) x = -1e30f;      // APP_ID = 0 impossible at first char
    if (t >= lengths[b]) x = 0.0f;         // padding rows zeroed before softmax
    float mx = x;
    #pragma unroll
    for (int o = 16; o > 0; o >>= 1) mx = fmaxf(mx, __shfl_xor_sync(0xffffffffu, mx, o));
    __shared__ float sm[4], ssum[4];
    int w = l >> 5;
    if ((l & 31) == 0) sm[w] = mx;
    __syncthreads();
    mx = fmaxf(fmaxf(sm[0], sm[1]), fmaxf(sm[2], sm[3]));
    float e = expf(x - mx);
    float s = e;
    #pragma unroll
    for (int o = 16; o > 0; o >>= 1) s += __shfl_xor_sync(0xffffffffu, s, o);
    if ((l & 31) == 0) ssum[w] = s;
    __syncthreads();
    s = ssum[0] + ssum[1] + ssum[2] + ssum[3];
    float lp = x - mx - logf(s);
    out[(size_t)m*LAB + l] = lp;
    if (dual) out[(size_t)NOUT + (size_t)m*LAB + l] = lp;
}

// ---------------- launch -------------------------------------------------------------
extern "C" void kernel_launch(void* const* d_in, const int* in_sizes, int n_in,
                              void* d_out, int out_size) {
    const float* enc       = (const float*)d_in[0];
    const int*   bd        = (const int*)  d_in[1];
    const int*   pos_seq   = (const int*)  d_in[2];
    const int*   lengths   = (const int*)  d_in[3];
    const float* w_ih      = (const float*)d_in[4];
    const float* w_hh      = (const float*)d_in[5];
    const float* b_ih      = (const float*)d_in[6];
    const float* b_hh      = (const float*)d_in[7];
    const float* pos_table = (const float*)d_in[8];
    const float* linear_w  = (const float*)d_in[9];
    const float* combine_w = (const float*)d_in[10];
    const float* combine_b = (const float*)d_in[11];
    float* out = (float*)d_out;
    int dual = (out_size >= 2*NOUT) ? 1 : 0;

    k_prep<<<2, 1024>>>(bd);
    k_off<<<1, 1>>>();
    k_transpose<<<512, 512>>>(w_hh);
    k_cse<<<dim3(BB, 4), 128>>>(enc);
    k_buildX<<<BT, XK>>>(pos_seq, pos_table);
    gemm_k<0><<<dim3(BT/128, 2), 256>>>(combine_w, combine_b, nullptr, nullptr, XK);
    gemm_k<1><<<dim3(BT/128, 8), 256>>>(w_ih,      b_ih,      b_hh,    nullptr, HH);
    k_scan2<<<BB/2, 256>>>();
    gemm_k<2><<<dim3(BT/128, 8), 256>>>(w_hh,      nullptr,   nullptr, nullptr, HH);
    k_lstm<<<BT*HH/1024, 1024>>>();
    gemm_k<3><<<dim3(BT/128, 1), 256>>>(linear_w,  nullptr,   nullptr, enc,     VK);
    k_softmax<<<BT, LAB>>>(lengths, out, dual);
}